// round 1
// baseline (speedup 1.0000x reference)
#include <cuda_runtime.h>
#include <cstdint>

// out[n,i,j,k] = sum_{a,b,c} x[n,a,b,c] w0[a,i] w1[b,j] w2[c,k]
// Implemented as 3 identical in-place smem stages per batch element:
//   out[q*32 + i] = sum_p in[p*1024 + q] * w[p*32 + i]
// (the output linear layout of each stage is exactly the next stage's input layout)

#define NTHREADS 512
#define FAC 32
#define ELEMS (32 * 32 * 32)            // 32768 floats per batch element
#define SMEM_FLOATS (ELEMS + 3 * FAC * FAC)
#define SMEM_BYTES (SMEM_FLOATS * 4)    // 143,360 B

// XOR swizzle at float4 granularity: bijective, consistent for all accesses.
__device__ __forceinline__ int swz(int f) { return f ^ (((f >> 5) & 7) << 2); }

__device__ __forceinline__ unsigned long long pack2(float v) {
    unsigned long long r;
    unsigned u = __float_as_uint(v);
    asm("mov.b64 %0, {%1, %1};" : "=l"(r) : "r"(u));
    return r;
}

__device__ __forceinline__ void ffma2(unsigned long long& acc,
                                      unsigned long long a,
                                      unsigned long long b) {
    // packed fp32x2 FMA (Blackwell); ptxas only emits FFMA2 from explicit PTX
    asm("fma.rn.f32x2 %0, %1, %2, %0;" : "+l"(acc) : "l"(a), "l"(b));
}

__global__ __launch_bounds__(NTHREADS, 1)
void kron3_kernel(const float* __restrict__ x,
                  const float* __restrict__ w0,
                  const float* __restrict__ w1,
                  const float* __restrict__ w2,
                  float* __restrict__ out) {
    extern __shared__ __align__(16) float smem[];
    float* buf = smem;                 // [ELEMS] xor-swizzled tensor buffer
    float* wsm = smem + ELEMS;         // [3*1024] weights, plain layout

    const int t = threadIdx.x;
    const long long nb = blockIdx.x;

    // --- load weights (broadcast-friendly plain layout) ---
    for (int i = t; i < FAC * FAC; i += NTHREADS) {
        wsm[i]        = w0[i];
        wsm[i + 1024] = w1[i];
        wsm[i + 2048] = w2[i];
    }

    // --- load x tile: coalesced float4, swizzled store ---
    const float4* xin = reinterpret_cast<const float4*>(x + nb * ELEMS);
    #pragma unroll
    for (int k = 0; k < ELEMS / 4 / NTHREADS; ++k) {   // 16 iters
        int v = t + k * NTHREADS;
        float4 val = xin[v];
        *reinterpret_cast<float4*>(buf + swz(4 * v)) = val;
    }
    __syncthreads();

    const int q0 = t;
    const int q1 = t + NTHREADS;
    // read base: swizzle of (p*1024 + q) only depends on q (p*32 % 8 == 0)
    const int rb0 = q0 ^ (((q0 >> 5) & 7) << 2);
    const int rb1 = q1 ^ (((q1 >> 5) & 7) << 2);
    // write xor constant: swizzle of (q*32 + i) xors i with (q&7)<<2
    const int cw0 = (q0 & 7) << 2;
    const int cw1 = (q1 & 7) << 2;

    #pragma unroll 1
    for (int s = 0; s < 3; ++s) {
        const float* w = wsm + s * FAC * FAC;

        unsigned long long acc0[16], acc1[16];
        #pragma unroll
        for (int j = 0; j < 16; ++j) { acc0[j] = 0ull; acc1[j] = 0ull; }

        #pragma unroll 4
        for (int p = 0; p < FAC; ++p) {
            unsigned long long vv0 = pack2(buf[rb0 + p * 1024]);
            unsigned long long vv1 = pack2(buf[rb1 + p * 1024]);
            const ulonglong2* wrow =
                reinterpret_cast<const ulonglong2*>(w + p * FAC);
            #pragma unroll
            for (int j4 = 0; j4 < 8; ++j4) {
                ulonglong2 wp = wrow[j4];        // LDS.128 broadcast
                ffma2(acc0[2 * j4],     vv0, wp.x);
                ffma2(acc0[2 * j4 + 1], vv0, wp.y);
                ffma2(acc1[2 * j4],     vv1, wp.x);
                ffma2(acc1[2 * j4 + 1], vv1, wp.y);
            }
        }
        __syncthreads();   // all reads of buf complete before overwrites

        #pragma unroll
        for (int j4 = 0; j4 < 8; ++j4) {
            {
                float4 v;
                v.x = __uint_as_float((unsigned)(acc0[2 * j4]       & 0xffffffffull));
                v.y = __uint_as_float((unsigned)(acc0[2 * j4]      >> 32));
                v.z = __uint_as_float((unsigned)(acc0[2 * j4 + 1]   & 0xffffffffull));
                v.w = __uint_as_float((unsigned)(acc0[2 * j4 + 1]  >> 32));
                *reinterpret_cast<float4*>(buf + q0 * FAC + ((4 * j4) ^ cw0)) = v;
            }
            {
                float4 v;
                v.x = __uint_as_float((unsigned)(acc1[2 * j4]       & 0xffffffffull));
                v.y = __uint_as_float((unsigned)(acc1[2 * j4]      >> 32));
                v.z = __uint_as_float((unsigned)(acc1[2 * j4 + 1]   & 0xffffffffull));
                v.w = __uint_as_float((unsigned)(acc1[2 * j4 + 1]  >> 32));
                *reinterpret_cast<float4*>(buf + q1 * FAC + ((4 * j4) ^ cw1)) = v;
            }
        }
        __syncthreads();   // writes visible before next stage reads
    }

    // --- store result: coalesced float4, swizzled read ---
    float4* op = reinterpret_cast<float4*>(out + nb * ELEMS);
    #pragma unroll
    for (int k = 0; k < ELEMS / 4 / NTHREADS; ++k) {   // 16 iters
        int v = t + k * NTHREADS;
        op[v] = *reinterpret_cast<const float4*>(buf + swz(4 * v));
    }
}

extern "C" void kernel_launch(void* const* d_in, const int* in_sizes, int n_in,
                              void* d_out, int out_size) {
    const float* x  = (const float*)d_in[0];
    const float* w0 = (const float*)d_in[1];
    const float* w1 = (const float*)d_in[2];
    const float* w2 = (const float*)d_in[3];
    float* out = (float*)d_out;

    int batch = in_sizes[0] / ELEMS;   // 1024

    cudaFuncSetAttribute(kron3_kernel,
                         cudaFuncAttributeMaxDynamicSharedMemorySize, SMEM_BYTES);
    kron3_kernel<<<batch, NTHREADS, SMEM_BYTES>>>(x, w0, w1, w2, out);
}

// round 5
// speedup vs baseline: 1.3480x; 1.3480x over previous
#include <cuda_runtime.h>
#include <cuda_bf16.h>
#include <cstdint>

// out[n,i,j,k] = sum_{a,b,c} x[n,a,b,c] w0[a,i] w1[b,j] w2[c,k]
// Three in-smem stages of D[q,i] = sum_p A[q,p] w[p,i]  (M=1024, N=32, K=32).
// Precision: split-bf16. A row = [hi(32)|lo(32)] bf16 = 128B SW128 row.
// B1 = w_hi, B2 = w_lo. Pairing: A_hi x w_hi, A_hi x w_lo, A_lo x w_hi
// (lo*w_lo ~2^-18 dropped). fp32 accumulation in mma.sync fragments.

#define NT 512
#define ELEMS 32768
#define A_OFF 0u
#define B_OFF 131072u            // A: 1024 rows * 128B
#define SCR_OFF 155648u          // B: 3 stages * 8KB (B1|B2)
#define SMEM_TOTAL 221184        // SCR: 64KB fp32 scratch

static __device__ __forceinline__ uint32_t swz(uint32_t b) { return b ^ ((b >> 3) & 0x70u); }

static __device__ __forceinline__ uint32_t smem_u32(const void* p) {
    uint32_t a;
    asm("{ .reg .u64 t; cvta.to.shared.u64 t, %1; cvt.u32.u64 %0, t; }" : "=r"(a) : "l"(p));
    return a;
}
static __device__ __forceinline__ void sts128(uint32_t a, uint32_t x, uint32_t y, uint32_t z, uint32_t w) {
    asm volatile("st.shared.v4.b32 [%0], {%1,%2,%3,%4};" :: "r"(a), "r"(x), "r"(y), "r"(z), "r"(w) : "memory");
}
static __device__ __forceinline__ void sts64f(uint32_t a, float x, float y) {
    asm volatile("st.shared.v2.f32 [%0], {%1,%2};" :: "r"(a), "f"(x), "f"(y) : "memory");
}
static __device__ __forceinline__ void sts16(uint32_t a, uint32_t v) {
    asm volatile("st.shared.b16 [%0], %1;" :: "r"(a), "h"((unsigned short)v) : "memory");
}
static __device__ __forceinline__ uint32_t lds32(uint32_t a) {
    uint32_t v; asm volatile("ld.shared.b32 %0, [%1];" : "=r"(v) : "r"(a)); return v;
}
static __device__ __forceinline__ float ldsf(uint32_t a) {
    float v; asm volatile("ld.shared.f32 %0, [%1];" : "=f"(v) : "r"(a)); return v;
}

// pack (e0 -> low half, e1 -> high half) as bf16x2
static __device__ __forceinline__ uint32_t cvt2(float e1, float e0) {
    uint32_t r;
    asm("cvt.rn.bf16x2.f32 %0, %1, %2;" : "=r"(r) : "f"(e1), "f"(e0));
    return r;
}
// split pair of fp32 into hi bf16x2 + lo bf16x2
static __device__ __forceinline__ void split2(float x0, float x1, uint32_t& h, uint32_t& l) {
    h = cvt2(x1, x0);
    float h0 = __uint_as_float(h << 16);
    float h1 = __uint_as_float(h & 0xffff0000u);
    l = cvt2(x1 - h1, x0 - h0);
}

static __device__ __forceinline__ void mma16816(float* c,
                                                uint32_t a0, uint32_t a1, uint32_t a2, uint32_t a3,
                                                uint32_t b0, uint32_t b1) {
    asm volatile(
        "mma.sync.aligned.m16n8k16.row.col.f32.bf16.bf16.f32 "
        "{%0,%1,%2,%3}, {%4,%5,%6,%7}, {%8,%9}, {%0,%1,%2,%3};"
        : "+f"(c[0]), "+f"(c[1]), "+f"(c[2]), "+f"(c[3])
        : "r"(a0), "r"(a1), "r"(a2), "r"(a3), "r"(b0), "r"(b1));
}

__global__ __launch_bounds__(NT, 1)
void kron3_mma_kernel(const float* __restrict__ x,
                      const float* __restrict__ w0,
                      const float* __restrict__ w1,
                      const float* __restrict__ w2,
                      float* __restrict__ out) {
    extern __shared__ __align__(16) char smem[];
    const uint32_t sb = smem_u32(smem);

    const int tid = threadIdx.x;
    const int w = tid >> 5;
    const int lane = tid & 31;
    const long long nb = blockIdx.x;

    // ---- weight prep: per stage, B1 rows = w_hi (first 64B), B2 rows = w_lo ----
    if (tid < 96) {
        const int s = tid >> 5;
        const int i = tid & 31;
        const float* ws = (s == 0) ? w0 : (s == 1) ? w1 : w2;
        const uint32_t b1 = sb + B_OFF + (uint32_t)s * 8192u;
        const uint32_t b2 = b1 + 4096u;
        #pragma unroll 4
        for (int p = 0; p < 32; ++p) {
            float v = ws[p * 32 + i];
            uint32_t hp = cvt2(0.0f, v);
            float hf = __uint_as_float(hp << 16);
            uint32_t lp = cvt2(0.0f, v - hf);
            uint32_t ro = (uint32_t)(i * 128 + 2 * p);
            sts16(b1 + swz(ro), hp & 0xffffu);
            sts16(b2 + swz(ro), lp & 0xffffu);
        }
    }

    // ---- prologue: x (global, coalesced) -> A rows (split hi|lo, SW128) ----
    {
        const float* xb = x + nb * ELEMS;
        #pragma unroll 1
        for (int rr = 0; rr < 2; ++rr) {
            const int q = tid + rr * NT;
            float v[32];
            #pragma unroll
            for (int p = 0; p < 32; ++p) v[p] = xb[p * 1024 + q];
            const uint32_t base = (uint32_t)q * 128u;
            #pragma unroll
            for (int j = 0; j < 4; ++j) {
                uint32_t h0, h1, h2, h3, l0, l1, l2, l3;
                split2(v[8 * j + 0], v[8 * j + 1], h0, l0);
                split2(v[8 * j + 2], v[8 * j + 3], h1, l1);
                split2(v[8 * j + 4], v[8 * j + 5], h2, l2);
                split2(v[8 * j + 6], v[8 * j + 7], h3, l3);
                sts128(sb + A_OFF + swz(base + 16u * j), h0, h1, h2, h3);
                sts128(sb + A_OFF + swz(base + 64u + 16u * j), l0, l1, l2, l3);
            }
        }
    }
    __syncthreads();

    // ---- 3 stages ----
    #pragma unroll 1
    for (int s = 0; s < 3; ++s) {
        // B fragments: bfr1 = w_hi, bfr2 = w_lo (k-blocks 0,1 only; values reused)
        uint32_t bfr1[4][2][2], bfr2[4][2][2];
        {
            const uint32_t b1 = sb + B_OFF + (uint32_t)s * 8192u;
            const uint32_t b2 = b1 + 4096u;
            #pragma unroll
            for (int nt = 0; nt < 4; ++nt)
                #pragma unroll
                for (int kb = 0; kb < 2; ++kb) {
                    uint32_t byte = (uint32_t)((nt * 8 + (lane >> 2)) * 128 + kb * 32 + (lane & 3) * 4);
                    bfr1[nt][kb][0] = lds32(b1 + swz(byte));
                    bfr1[nt][kb][1] = lds32(b1 + swz(byte + 16u));
                    bfr2[nt][kb][0] = lds32(b2 + swz(byte));
                    bfr2[nt][kb][1] = lds32(b2 + swz(byte + 16u));
                }
        }

        float cc[4][4][4];
        #pragma unroll
        for (int mt = 0; mt < 4; ++mt)
            #pragma unroll
            for (int nt = 0; nt < 4; ++nt)
                #pragma unroll
                for (int e = 0; e < 4; ++e) cc[mt][nt][e] = 0.0f;

        #pragma unroll
        for (int mt = 0; mt < 4; ++mt) {
            const uint32_t qlo = (uint32_t)(w * 64 + mt * 16 + (lane >> 2));
            #pragma unroll
            for (int kb = 0; kb < 4; ++kb) {   // kb 0,1 = A_hi; kb 2,3 = A_lo
                const uint32_t kbyte = (uint32_t)(kb * 32 + (lane & 3) * 4);
                uint32_t a0 = lds32(sb + A_OFF + swz(qlo * 128u + kbyte));
                uint32_t a1 = lds32(sb + A_OFF + swz((qlo + 8u) * 128u + kbyte));
                uint32_t a2 = lds32(sb + A_OFF + swz(qlo * 128u + kbyte + 16u));
                uint32_t a3 = lds32(sb + A_OFF + swz((qlo + 8u) * 128u + kbyte + 16u));
                const int kk = kb & 1;
                #pragma unroll
                for (int nt = 0; nt < 4; ++nt)
                    mma16816(cc[mt][nt], a0, a1, a2, a3, bfr1[nt][kk][0], bfr1[nt][kk][1]);
                if (kb < 2) {
                    #pragma unroll
                    for (int nt = 0; nt < 4; ++nt)
                        mma16816(cc[mt][nt], a0, a1, a2, a3, bfr2[nt][kk][0], bfr2[nt][kk][1]);
                }
            }
        }

        if (s < 2) {
            // epilogue: c regs -> scratch (D layout) -> permuted A' rows, in 2 halves
            #pragma unroll 1
            for (int h = 0; h < 2; ++h) {
                if ((w >> 3) == h) {
                    #pragma unroll
                    for (int mt = 0; mt < 4; ++mt) {
                        const uint32_t qloc = (uint32_t)((w * 64 + mt * 16 + (lane >> 2)) & 511);
                        #pragma unroll
                        for (int nt = 0; nt < 4; ++nt) {
                            const uint32_t i0 = (uint32_t)(nt * 8 + (lane & 3) * 2);
                            sts64f(sb + SCR_OFF + swz(qloc * 128u + i0 * 4u),
                                   cc[mt][nt][0], cc[mt][nt][1]);
                            sts64f(sb + SCR_OFF + swz((qloc + 8u) * 128u + i0 * 4u),
                                   cc[mt][nt][2], cc[mt][nt][3]);
                        }
                    }
                }
                __syncthreads();
                // gather: thread owns new rows r2 = tid, tid+512; writes A' cols [16h,16h+16)
                #pragma unroll 1
                for (int rr = 0; rr < 2; ++rr) {
                    const int r2 = tid + rr * NT;
                    const uint32_t rhi = (uint32_t)(r2 >> 5);
                    const uint32_t il = (uint32_t)(r2 & 31);
                    float val[16];
                    #pragma unroll
                    for (int j = 0; j < 16; ++j)
                        val[j] = ldsf(sb + SCR_OFF + swz(((uint32_t)j * 32u + rhi) * 128u + il * 4u));
                    uint32_t hw[8], lw[8];
                    #pragma unroll
                    for (int e = 0; e < 8; ++e)
                        split2(val[2 * e], val[2 * e + 1], hw[e], lw[e]);
                    const uint32_t rbase = (uint32_t)r2 * 128u + (uint32_t)(32 * h);
                    sts128(sb + A_OFF + swz(rbase),        hw[0], hw[1], hw[2], hw[3]);
                    sts128(sb + A_OFF + swz(rbase + 16u),  hw[4], hw[5], hw[6], hw[7]);
                    sts128(sb + A_OFF + swz(rbase + 64u),  lw[0], lw[1], lw[2], lw[3]);
                    sts128(sb + A_OFF + swz(rbase + 80u),  lw[4], lw[5], lw[6], lw[7]);
                }
                __syncthreads();
            }
        } else {
            // final: c regs -> global out (fp32), 8B stores filling exact 32B sectors
            float* ob = out + nb * ELEMS;
            #pragma unroll
            for (int mt = 0; mt < 4; ++mt) {
                const int q = w * 64 + mt * 16 + (lane >> 2);
                #pragma unroll
                for (int nt = 0; nt < 4; ++nt) {
                    const int i0 = nt * 8 + (lane & 3) * 2;
                    float2 v0; v0.x = cc[mt][nt][0]; v0.y = cc[mt][nt][1];
                    float2 v1; v1.x = cc[mt][nt][2]; v1.y = cc[mt][nt][3];
                    *reinterpret_cast<float2*>(ob + q * 32 + i0) = v0;
                    *reinterpret_cast<float2*>(ob + (q + 8) * 32 + i0) = v1;
                }
            }
        }
    }
}

extern "C" void kernel_launch(void* const* d_in, const int* in_sizes, int n_in,
                              void* d_out, int out_size) {
    const float* x  = (const float*)d_in[0];
    const float* w0 = (const float*)d_in[1];
    const float* w1 = (const float*)d_in[2];
    const float* w2 = (const float*)d_in[3];
    float* out = (float*)d_out;

    int batch = in_sizes[0] / ELEMS;   // 1024

    cudaFuncSetAttribute(kron3_mma_kernel,
                         cudaFuncAttributeMaxDynamicSharedMemorySize, SMEM_TOTAL);
    kron3_mma_kernel<<<batch, NT, SMEM_TOTAL>>>(x, w0, w1, w2, out);
}